// round 1
// baseline (speedup 1.0000x reference)
#include <cuda_runtime.h>
#include <cstdint>

// Problem constants
#define NB      16
#define NN      16384
#define NS      256
#define NKS     16
#define C       288
#define K0      291
#define SB0     296              // padded row stride for H0 (float4-tile safe)
#define PTOT    (NB*NS*NKS)      // 65536 pixels

// ---------------- scratch (static device globals; no allocation) ----------------
__device__ float d_H0[(size_t)PTOT * SB0];
__device__ float d_H1[(size_t)PTOT * C];
__device__ float d_H2[(size_t)PTOT * C];
__device__ float d_H3[(size_t)PTOT * C];
__device__ int   d_idx[PTOT];
__device__ float d_newxyz[NB * NS * 3];

// =================================================================================
// 1) Farthest point sampling: one block per batch, xyz in smem (192KB), dist in regs
// =================================================================================
__global__ __launch_bounds__(1024, 1) void fps_kernel(const float* __restrict__ xyz,
                                                      float* __restrict__ out_newxyz,
                                                      float* __restrict__ out_inds)
{
    extern __shared__ float sm[];
    float* sx = sm;
    float* sy = sm + NN;
    float* sz = sm + 2 * NN;
    __shared__ float redV[32];
    __shared__ int   redI[32];
    __shared__ int   sCur;

    const int b   = blockIdx.x;
    const int tid = threadIdx.x;
    const float* base = xyz + (size_t)b * NN * 3;

    for (int u = tid; u < NN * 3; u += 1024) {
        float v = base[u];
        int n = u / 3, c = u - 3 * n;
        if (c == 0) sx[n] = v; else if (c == 1) sy[n] = v; else sz[n] = v;
    }
    float dist[16];
#pragma unroll
    for (int i = 0; i < 16; i++) dist[i] = 1e10f;
    __syncthreads();

    int cur = 0;
    for (int it = 0; it < NS; ++it) {
        float cx = sx[cur], cy = sy[cur], cz = sz[cur];
        if (tid == 0) {
            out_inds[b * NS + it] = (float)cur;
            int o3 = (b * NS + it) * 3;
            out_newxyz[o3] = cx; out_newxyz[o3 + 1] = cy; out_newxyz[o3 + 2] = cz;
            d_newxyz[o3]   = cx; d_newxyz[o3 + 1]   = cy; d_newxyz[o3 + 2]   = cz;
        }
        float bv = -1.0f; int bi = 0;
#pragma unroll
        for (int i = 0; i < 16; i++) {
            int n = i * 1024 + tid;
            float dx = sx[n] - cx, dy = sy[n] - cy, dz = sz[n] - cz;
            float d  = dx * dx + dy * dy + dz * dz;
            float dm = fminf(dist[i], d);
            dist[i] = dm;
            if (dm > bv) { bv = dm; bi = n; }      // within-thread: n ascending => first max kept
        }
        // warp reduce: max value, tie -> lowest index (jnp.argmax semantics)
#pragma unroll
        for (int off = 16; off; off >>= 1) {
            float v2 = __shfl_down_sync(0xffffffffu, bv, off);
            int   i2 = __shfl_down_sync(0xffffffffu, bi, off);
            if (v2 > bv || (v2 == bv && i2 < bi)) { bv = v2; bi = i2; }
        }
        if ((tid & 31) == 0) { redV[tid >> 5] = bv; redI[tid >> 5] = bi; }
        __syncthreads();
        if (tid < 32) {
            bv = redV[tid]; bi = redI[tid];
#pragma unroll
            for (int off = 16; off; off >>= 1) {
                float v2 = __shfl_down_sync(0xffffffffu, bv, off);
                int   i2 = __shfl_down_sync(0xffffffffu, bi, off);
                if (v2 > bv || (v2 == bv && i2 < bi)) { bv = v2; bi = i2; }
            }
            if (tid == 0) sCur = bi;
        }
        __syncthreads();
        cur = sCur;
    }
}

// =================================================================================
// 2) Ball query: one warp per centroid, early exit after 16 in-radius points
// =================================================================================
__global__ __launch_bounds__(512) void ballq_kernel(const float* __restrict__ xyz)
{
    __shared__ int slots[16][16];
    const int wl   = threadIdx.x >> 5;
    const int lane = threadIdx.x & 31;
    const int w    = blockIdx.x * 16 + wl;       // (b*256 + s)
    const int b    = w >> 8;
    const float R2 = (float)(0.3 * 0.3);         // exact constant XLA compares against
    const int o3   = w * 3;
    const float nx = d_newxyz[o3], ny = d_newxyz[o3 + 1], nz = d_newxyz[o3 + 2];
    const float* pb = xyz + (size_t)b * NN * 3;

    int cnt = 0;
    for (int basei = 0; basei < NN && cnt < NKS; basei += 32) {
        int n = basei + lane;
        float dx = pb[3 * n] - nx, dy = pb[3 * n + 1] - ny, dz = pb[3 * n + 2] - nz;
        float d2 = dx * dx + dy * dy + dz * dz;
        bool in  = d2 < R2;
        unsigned m = __ballot_sync(0xffffffffu, in);
        int pos = cnt + __popc(m & ((1u << lane) - 1u));
        if (in && pos < NKS) slots[wl][pos] = n;
        cnt += __popc(m);
    }
    __syncwarp();
    int first = slots[wl][0];
    if (lane < NKS && lane >= cnt) slots[wl][lane] = first;   // pad with first found
    __syncwarp();
    if (lane < NKS) d_idx[w * NKS + lane] = slots[wl][lane];
}

// =================================================================================
// 3) Gather: build H0[p][c] (c: 0..2 rel-xyz/R, 3..290 features, 291..295 zero pad)
// =================================================================================
__global__ __launch_bounds__(256) void gather_kernel(const float* __restrict__ xyz,
                                                     const float* __restrict__ feat)
{
    const int p    = blockIdx.x * 8 + (threadIdx.x >> 5);
    const int lane = threadIdx.x & 31;
    const int b    = p >> 12;
    const int s    = (p >> 4) & 255;
    const int j    = d_idx[p];
    float* row = d_H0 + (size_t)p * SB0;

    if (lane < 3) {
        float gv = xyz[((size_t)b * NN + j) * 3 + lane];
        float cv = d_newxyz[(b * NS + s) * 3 + lane];
        row[lane] = (gv - cv) / 0.3f;
    } else if (lane < 8) {
        row[288 + lane] = 0.0f;                  // pads c=291..295 (finite for float4 tiles)
    }
    const float* fb = feat + (size_t)b * C * NN + j;
#pragma unroll
    for (int r = 0; r < 9; r++) {
        int c = lane + 32 * r;
        row[3 + c] = fb[(size_t)c * NN];
    }
}

// =================================================================================
// 4) GEMM + BN + ReLU (fp32, packed fma.rn.f32x2 => 2x FFMA-pipe rate on sm_103a)
//    out[p][o] = relu((sum_c W[o][c]*Hin[p][c] - m[o])*g[o]*rsqrt(v[o]+eps) + b[o])
//    Tiles: 96(o) x 128(p) x 8(c), 256 threads, 6x8 micro-tile, double-buffered smem
// =================================================================================
__device__ __forceinline__ void ffma2(unsigned long long& d, unsigned long long a,
                                      unsigned long long b)
{
    asm("fma.rn.f32x2 %0, %1, %2, %0;" : "+l"(d) : "l"(a), "l"(b));
}
__device__ __forceinline__ unsigned long long pack2(float x)
{
    unsigned long long r;
    asm("mov.b64 %0, {%1, %1};" : "=l"(r) : "f"(x));
    return r;
}

template <int K, int SB>
__global__ __launch_bounds__(256) void gemm_bn_relu(const float* __restrict__ W,
                                                    const float* __restrict__ Hin,
                                                    float* __restrict__ Hout,
                                                    const float* __restrict__ gg,
                                                    const float* __restrict__ bbp,
                                                    const float* __restrict__ mmp,
                                                    const float* __restrict__ vvp)
{
    __shared__ float As[2][8][100];
    __shared__ float Bs[2][8][132];
    __shared__ float St[128][33];

    const int t  = threadIdx.x;
    const int tx = t & 15, ty = t >> 4;
    const int p0 = blockIdx.x * 128;
    const int o0 = blockIdx.y * 96;
    const int NT = (K + 7) / 8;
    const int pr = t >> 1, cc = t & 1;

    unsigned long long acc[6][4];
#pragma unroll
    for (int i = 0; i < 6; i++)
#pragma unroll
        for (int j = 0; j < 4; j++) acc[i][j] = 0ull;

    auto compute = [&](int cb) {
#pragma unroll
        for (int kk = 0; kk < 8; kk++) {
            float2 a01 = *reinterpret_cast<const float2*>(&As[cb][kk][ty * 6]);
            float2 a23 = *reinterpret_cast<const float2*>(&As[cb][kk][ty * 6 + 2]);
            float2 a45 = *reinterpret_cast<const float2*>(&As[cb][kk][ty * 6 + 4]);
            ulonglong2 b0 = *reinterpret_cast<const ulonglong2*>(&Bs[cb][kk][tx * 8]);
            ulonglong2 b1 = *reinterpret_cast<const ulonglong2*>(&Bs[cb][kk][tx * 8 + 4]);
            float av[6] = {a01.x, a01.y, a23.x, a23.y, a45.x, a45.y};
#pragma unroll
            for (int i = 0; i < 6; i++) {
                unsigned long long pa = pack2(av[i]);
                ffma2(acc[i][0], pa, b0.x);
                ffma2(acc[i][1], pa, b0.y);
                ffma2(acc[i][2], pa, b1.x);
                ffma2(acc[i][3], pa, b1.y);
            }
        }
    };

    // tile 0 direct
    {
#pragma unroll
        for (int i = 0; i < 3; i++) {
            int e = t + 256 * i;
            int oR = e >> 3, kk = e & 7;
            As[0][kk][oR] = (kk < K) ? W[(o0 + oR) * K + kk] : 0.f;
        }
        float4 bv4 = *reinterpret_cast<const float4*>(&Hin[(size_t)(p0 + pr) * SB + 4 * cc]);
        Bs[0][4 * cc + 0][pr] = bv4.x; Bs[0][4 * cc + 1][pr] = bv4.y;
        Bs[0][4 * cc + 2][pr] = bv4.z; Bs[0][4 * cc + 3][pr] = bv4.w;
    }
    __syncthreads();

    int curb = 0;
    for (int tl = 1; tl < NT; ++tl) {
        const int c0 = tl * 8;
        float aR[3];
#pragma unroll
        for (int i = 0; i < 3; i++) {
            int e = t + 256 * i;
            int oR = e >> 3, kk = e & 7;
            aR[i] = (c0 + kk < K) ? W[(o0 + oR) * K + c0 + kk] : 0.f;
        }
        float4 bv4 = *reinterpret_cast<const float4*>(&Hin[(size_t)(p0 + pr) * SB + c0 + 4 * cc]);

        compute(curb);

        const int nb = curb ^ 1;
#pragma unroll
        for (int i = 0; i < 3; i++) {
            int e = t + 256 * i;
            As[nb][e & 7][e >> 3] = aR[i];
        }
        Bs[nb][4 * cc + 0][pr] = bv4.x; Bs[nb][4 * cc + 1][pr] = bv4.y;
        Bs[nb][4 * cc + 2][pr] = bv4.z; Bs[nb][4 * cc + 3][pr] = bv4.w;
        __syncthreads();
        curb = nb;
    }
    compute(curb);

    // epilogue: BN + ReLU
    float ov[6][8];
#pragma unroll
    for (int i = 0; i < 6; i++) {
        int oA = o0 + ty * 6 + i;
        float sc = gg[oA] * rsqrtf(vvp[oA] + 1e-5f);
        float mo = mmp[oA], bo = bbp[oA];
#pragma unroll
        for (int jj = 0; jj < 4; jj++) {
            float2 pq = *reinterpret_cast<float2*>(&acc[i][jj]);
            ov[i][2 * jj]     = fmaxf((pq.x - mo) * sc + bo, 0.f);
            ov[i][2 * jj + 1] = fmaxf((pq.y - mo) * sc + bo, 0.f);
        }
    }
    // coalesced transposed store through smem, 32-wide o slices
    __syncthreads();
    for (int sl = 0; sl < 3; ++sl) {
#pragma unroll
        for (int i = 0; i < 6; i++) {
            int orr = ty * 6 + i;
            if ((orr >> 5) == sl) {
#pragma unroll
                for (int j = 0; j < 8; j++) St[tx * 8 + j][orr & 31] = ov[i][j];
            }
        }
        __syncthreads();
        for (int q = t; q < 128 * 32; q += 256) {
            int prr = q >> 5, oc = q & 31;
            Hout[(size_t)(p0 + prr) * C + o0 + sl * 32 + oc] = St[prr][oc];
        }
        __syncthreads();
    }
}

// =================================================================================
// 5) Max over the 16 samples -> new_features (B, C, S)
// =================================================================================
__global__ __launch_bounds__(288) void maxk_kernel(float* __restrict__ out_feat)
{
    const int ps = blockIdx.x;          // b*256 + s
    const int p0 = ps * NKS;
    const int b  = ps >> 8, s = ps & 255;
    const int o  = threadIdx.x;
    float mv = d_H3[(size_t)p0 * C + o];
#pragma unroll
    for (int k = 1; k < NKS; k++) mv = fmaxf(mv, d_H3[(size_t)(p0 + k) * C + o]);
    out_feat[((size_t)b * C + o) * NS + s] = mv;
}

// =================================================================================
extern "C" void kernel_launch(void* const* d_in, const int* in_sizes, int n_in,
                              void* d_out, int out_size)
{
    const float* xyz  = (const float*)d_in[0];
    const float* feat = (const float*)d_in[1];
    const float* W0 = (const float*)d_in[2];
    const float* g0 = (const float*)d_in[3];
    const float* b0 = (const float*)d_in[4];
    const float* m0 = (const float*)d_in[5];
    const float* v0 = (const float*)d_in[6];
    const float* W1 = (const float*)d_in[7];
    const float* g1 = (const float*)d_in[8];
    const float* b1 = (const float*)d_in[9];
    const float* m1 = (const float*)d_in[10];
    const float* v1 = (const float*)d_in[11];
    const float* W2 = (const float*)d_in[12];
    const float* g2 = (const float*)d_in[13];
    const float* b2 = (const float*)d_in[14];
    const float* m2 = (const float*)d_in[15];
    const float* v2 = (const float*)d_in[16];

    float* out        = (float*)d_out;
    float* out_newxyz = out;                                   // (16,256,3)
    float* out_feat   = out + NB * NS * 3;                     // (16,288,256)
    float* out_inds   = out + NB * NS * 3 + (size_t)NB * C * NS; // (16,256) as float

    float *H0p, *H1p, *H2p, *H3p;
    cudaGetSymbolAddress((void**)&H0p, d_H0);
    cudaGetSymbolAddress((void**)&H1p, d_H1);
    cudaGetSymbolAddress((void**)&H2p, d_H2);
    cudaGetSymbolAddress((void**)&H3p, d_H3);

    cudaFuncSetAttribute(fps_kernel, cudaFuncAttributeMaxDynamicSharedMemorySize,
                         3 * NN * (int)sizeof(float));

    fps_kernel<<<NB, 1024, 3 * NN * sizeof(float)>>>(xyz, out_newxyz, out_inds);
    ballq_kernel<<<NB * NS / 16, 512>>>(xyz);
    gather_kernel<<<PTOT / 8, 256>>>(xyz, feat);
    gemm_bn_relu<K0, SB0><<<dim3(PTOT / 128, 3), 256>>>(W0, H0p, H1p, g0, b0, m0, v0);
    gemm_bn_relu<C, C><<<dim3(PTOT / 128, 3), 256>>>(W1, H1p, H2p, g1, b1, m1, v1);
    gemm_bn_relu<C, C><<<dim3(PTOT / 128, 3), 256>>>(W2, H2p, H3p, g2, b2, m2, v2);
    maxk_kernel<<<NB * NS, C>>>(out_feat);
}

// round 5
// speedup vs baseline: 1.7773x; 1.7773x over previous
#include <cuda_runtime.h>
#include <cuda_bf16.h>
#include <cstdint>

// Problem constants
#define NB      16
#define NN      16384
#define NS      256
#define NKS     16
#define C       288
#define PTOT    (NB*NS*NKS)      // 65536 pixels
#define NCHUNK  5                // K padded to 320 = 5 chunks of 64
#define TM      128              // pixels per GEMM CTA
#define NTILES  (PTOT/TM)        // 512

// byte sizes
#define A_CHUNK_B   (TM*128)             // 16384  (128 rows x 64 bf16)
#define A_TILE_B    (NCHUNK*A_CHUNK_B)   // 81920 per tile per array
#define B_CHUNK_B   (C*128)              // 36864  (288 rows x 64 bf16)
#define W_LAYER_B   (NCHUNK*B_CHUNK_B)   // 184320
#define BH_B        (144*128)            // 18432 per CTA half per chunk

// SMEM stage layout (all 1024-multiples)
#define SA_H  0u
#define SA_L  16384u
#define SB_H  32768u
#define SB_L  51200u
#define STG   69632u
#define DYN_SMEM (2*STG + 1024)          // 140288

// SW128 swizzle (within a 1024-aligned region)
#define SWZ(o) ((o) ^ (((o) >> 3) & 0x70))

// ---------------- scratch ----------------
__device__ __align__(1024) unsigned char d_Xhi[(size_t)NTILES * A_TILE_B];
__device__ __align__(1024) unsigned char d_Xlo[(size_t)NTILES * A_TILE_B];
__device__ __align__(1024) unsigned char d_Yhi[(size_t)NTILES * A_TILE_B];
__device__ __align__(1024) unsigned char d_Ylo[(size_t)NTILES * A_TILE_B];
__device__ __align__(1024) unsigned char d_Whi[3 * W_LAYER_B];
__device__ __align__(1024) unsigned char d_Wlo[3 * W_LAYER_B];
__device__ int   d_idx[PTOT];
__device__ float d_newxyz[NB * NS * 3];

// ---------------- PTX helpers (all compute_80-era: safe on compute_103) ----------
__device__ __forceinline__ uint32_t smem_u32(const void* p) {
    uint32_t a;
    asm("{ .reg .u64 t; cvta.to.shared.u64 t, %1; cvt.u32.u64 %0, t; }" : "=r"(a) : "l"(p));
    return a;
}
__device__ __forceinline__ void cp16(uint32_t s, const void* g) {
    asm volatile("cp.async.cg.shared.global [%0], [%1], 16;" :: "r"(s), "l"(g) : "memory");
}
#define CP_COMMIT() asm volatile("cp.async.commit_group;" ::: "memory")
template <int N> __device__ __forceinline__ void cp_wait() {
    asm volatile("cp.async.wait_group %0;" :: "n"(N) : "memory");
}
__device__ __forceinline__ void ldmx4(uint32_t* r, uint32_t a) {
    asm volatile("ldmatrix.sync.aligned.m8n8.x4.shared.b16 {%0,%1,%2,%3}, [%4];"
                 : "=r"(r[0]), "=r"(r[1]), "=r"(r[2]), "=r"(r[3]) : "r"(a));
}
__device__ __forceinline__ void ldmx2(uint32_t* r, uint32_t a) {
    asm volatile("ldmatrix.sync.aligned.m8n8.x2.shared.b16 {%0,%1}, [%2];"
                 : "=r"(r[0]), "=r"(r[1]) : "r"(a));
}
__device__ __forceinline__ void mma16816(float* c, const uint32_t* a, const uint32_t* b) {
    asm volatile("mma.sync.aligned.m16n8k16.row.col.f32.bf16.bf16.f32 "
                 "{%0,%1,%2,%3}, {%4,%5,%6,%7}, {%8,%9}, {%0,%1,%2,%3};"
                 : "+f"(c[0]), "+f"(c[1]), "+f"(c[2]), "+f"(c[3])
                 : "r"(a[0]), "r"(a[1]), "r"(a[2]), "r"(a[3]), "r"(b[0]), "r"(b[1]));
}
__device__ __forceinline__ void split_bf(float x, __nv_bfloat16& h, __nv_bfloat16& l) {
    h = __float2bfloat16(x);
    l = __float2bfloat16(x - __bfloat162float(h));
}
__device__ __forceinline__ uint32_t pack_bf(__nv_bfloat16 a, __nv_bfloat16 b) {
    return (uint32_t)__bfloat16_as_ushort(a) | ((uint32_t)__bfloat16_as_ushort(b) << 16);
}

// =================================================================================
// 1) FPS (unchanged — passing in R1)
// =================================================================================
__global__ __launch_bounds__(1024, 1) void fps_kernel(const float* __restrict__ xyz,
                                                      float* __restrict__ out_newxyz,
                                                      float* __restrict__ out_inds)
{
    extern __shared__ float sm[];
    float* sx = sm; float* sy = sm + NN; float* sz = sm + 2 * NN;
    __shared__ float redV[32];
    __shared__ int   redI[32];
    __shared__ int   sCur;

    const int b = blockIdx.x, tid = threadIdx.x;
    const float* base = xyz + (size_t)b * NN * 3;
    for (int u = tid; u < NN * 3; u += 1024) {
        float v = base[u];
        int n = u / 3, c = u - 3 * n;
        if (c == 0) sx[n] = v; else if (c == 1) sy[n] = v; else sz[n] = v;
    }
    float dist[16];
#pragma unroll
    for (int i = 0; i < 16; i++) dist[i] = 1e10f;
    __syncthreads();

    int cur = 0;
    for (int it = 0; it < NS; ++it) {
        float cx = sx[cur], cy = sy[cur], cz = sz[cur];
        if (tid == 0) {
            out_inds[b * NS + it] = (float)cur;
            int o3 = (b * NS + it) * 3;
            out_newxyz[o3] = cx; out_newxyz[o3 + 1] = cy; out_newxyz[o3 + 2] = cz;
            d_newxyz[o3]   = cx; d_newxyz[o3 + 1]   = cy; d_newxyz[o3 + 2]   = cz;
        }
        float bv = -1.0f; int bi = 0;
#pragma unroll
        for (int i = 0; i < 16; i++) {
            int n = i * 1024 + tid;
            float dx = sx[n] - cx, dy = sy[n] - cy, dz = sz[n] - cz;
            float d = dx * dx + dy * dy + dz * dz;
            float dm = fminf(dist[i], d);
            dist[i] = dm;
            if (dm > bv) { bv = dm; bi = n; }
        }
#pragma unroll
        for (int off = 16; off; off >>= 1) {
            float v2 = __shfl_down_sync(0xffffffffu, bv, off);
            int   i2 = __shfl_down_sync(0xffffffffu, bi, off);
            if (v2 > bv || (v2 == bv && i2 < bi)) { bv = v2; bi = i2; }
        }
        if ((tid & 31) == 0) { redV[tid >> 5] = bv; redI[tid >> 5] = bi; }
        __syncthreads();
        if (tid < 32) {
            bv = redV[tid]; bi = redI[tid];
#pragma unroll
            for (int off = 16; off; off >>= 1) {
                float v2 = __shfl_down_sync(0xffffffffu, bv, off);
                int   i2 = __shfl_down_sync(0xffffffffu, bi, off);
                if (v2 > bv || (v2 == bv && i2 < bi)) { bv = v2; bi = i2; }
            }
            if (tid == 0) sCur = bi;
        }
        __syncthreads();
        cur = sCur;
    }
}

// =================================================================================
// 2) Ball query (unchanged)
// =================================================================================
__global__ __launch_bounds__(512) void ballq_kernel(const float* __restrict__ xyz)
{
    __shared__ int slots[16][16];
    const int wl = threadIdx.x >> 5, lane = threadIdx.x & 31;
    const int w  = blockIdx.x * 16 + wl;
    const int b  = w >> 8;
    const float R2 = (float)(0.3 * 0.3);
    const int o3 = w * 3;
    const float nx = d_newxyz[o3], ny = d_newxyz[o3 + 1], nz = d_newxyz[o3 + 2];
    const float* pb = xyz + (size_t)b * NN * 3;

    int cnt = 0;
    for (int basei = 0; basei < NN && cnt < NKS; basei += 32) {
        int n = basei + lane;
        float dx = pb[3 * n] - nx, dy = pb[3 * n + 1] - ny, dz = pb[3 * n + 2] - nz;
        float d2 = dx * dx + dy * dy + dz * dz;
        bool in = d2 < R2;
        unsigned m = __ballot_sync(0xffffffffu, in);
        int pos = cnt + __popc(m & ((1u << lane) - 1u));
        if (in && pos < NKS) slots[wl][pos] = n;
        cnt += __popc(m);
    }
    __syncwarp();
    int first = slots[wl][0];
    if (lane < NKS && lane >= cnt) slots[wl][lane] = first;
    __syncwarp();
    if (lane < NKS) d_idx[w * NKS + lane] = slots[wl][lane];
}

// =================================================================================
// 3) Weight prep: fp32 W -> bf16 hi/lo, chunked SW128 layout, layer0 col-permute
//    Layer0 col order: 0..287 = features (W0 col c+3), 288..290 = xyz (W0 col c-288)
// =================================================================================
__global__ __launch_bounds__(256) void wprep_kernel(const float* __restrict__ W, int Kdim,
                                                    int perm0, unsigned char* __restrict__ whi,
                                                    unsigned char* __restrict__ wlo)
{
    int id = blockIdx.x * 256 + threadIdx.x;
    if (id >= C * 40) return;
    int o = id / 40, u = id % 40;
    uint32_t h[4], l[4];
#pragma unroll
    for (int e = 0; e < 4; e++) {
        __nv_bfloat16 hh[2], ll[2];
#pragma unroll
        for (int q = 0; q < 2; q++) {
            int c = u * 8 + e * 2 + q;
            int src;
            if (perm0) src = (c < 288) ? c + 3 : ((c < 291) ? c - 288 : -1);
            else       src = (c < Kdim) ? c : -1;
            float v = (src >= 0) ? W[o * Kdim + src] : 0.0f;
            split_bf(v, hh[q], ll[q]);
        }
        h[e] = pack_bf(hh[0], hh[1]);
        l[e] = pack_bf(ll[0], ll[1]);
    }
    size_t off = (size_t)(u / 8) * B_CHUNK_B + SWZ((uint32_t)(o * 128 + (u % 8) * 16));
    *reinterpret_cast<uint4*>(whi + off) = make_uint4(h[0], h[1], h[2], h[3]);
    *reinterpret_cast<uint4*>(wlo + off) = make_uint4(l[0], l[1], l[2], l[3]);
}

// =================================================================================
// 4) Gather: build layer-0 A tiles (bf16 hi/lo, swizzled chunk layout)
//    cols 0..287 features, 288..290 rel-xyz/0.3, 291..319 zero
// =================================================================================
__global__ __launch_bounds__(128) void gather_kernel(const float* __restrict__ xyz,
                                                     const float* __restrict__ feat)
{
    __shared__ __align__(16) __nv_bfloat16 sH[4][320];
    __shared__ __align__(16) __nv_bfloat16 sL[4][320];
    const int wid = threadIdx.x >> 5, lane = threadIdx.x & 31;
    const int p = blockIdx.x * 4 + wid;
    const int b = p >> 12, s = (p >> 4) & 255;
    const int j = d_idx[p];

    const float* fb = feat + (size_t)b * C * NN + j;
#pragma unroll
    for (int r = 0; r < 9; r++) {
        int c = lane + 32 * r;
        float f = fb[(size_t)c * NN];
        __nv_bfloat16 h, l; split_bf(f, h, l);
        sH[wid][c] = h; sL[wid][c] = l;
    }
    if (lane < 3) {
        float gv = xyz[((size_t)b * NN + j) * 3 + lane];
        float cv = d_newxyz[(b * NS + s) * 3 + lane];
        float rel = (gv - cv) / 0.3f;
        __nv_bfloat16 h, l; split_bf(rel, h, l);
        sH[wid][288 + lane] = h; sL[wid][288 + lane] = l;
    } else {
        sH[wid][288 + lane] = __ushort_as_bfloat16(0);
        sL[wid][288 + lane] = __ushort_as_bfloat16(0);
    }
    __syncwarp();

    const size_t tbase = (size_t)(p >> 7) * A_TILE_B;
    const int row = p & 127;
    const char* srcH = reinterpret_cast<const char*>(&sH[wid][0]);
    const char* srcL = reinterpret_cast<const char*>(&sL[wid][0]);
#pragma unroll
    for (int u = lane; u < 40; u += 32) {
        size_t off = tbase + (size_t)(u / 8) * A_CHUNK_B + SWZ((uint32_t)(row * 128 + (u % 8) * 16));
        *reinterpret_cast<uint4*>(d_Xhi + off) = *reinterpret_cast<const uint4*>(srcH + u * 16);
        *reinterpret_cast<uint4*>(d_Xlo + off) = *reinterpret_cast<const uint4*>(srcL + u * 16);
    }
}

// =================================================================================
// 5) GEMM + BN + ReLU via mma.sync bf16 hi/lo 3-product split, fp32 accum.
//    CTA: 128 px x 144 outs, grid (512, 2). 8 warps: wr=w&3 (32 px), wc=w>>2 (72 outs).
//    LAST: fused 16-sample max-pool epilogue.
// =================================================================================
template <bool LAST>
__global__ __launch_bounds__(256, 1) void mma_gemm(const unsigned char* __restrict__ Ahi,
                                                   const unsigned char* __restrict__ Alo,
                                                   const unsigned char* __restrict__ Bhi,
                                                   const unsigned char* __restrict__ Blo,
                                                   unsigned char* __restrict__ OutHi,
                                                   unsigned char* __restrict__ OutLo,
                                                   float* __restrict__ OutFeat,
                                                   const float* __restrict__ gg,
                                                   const float* __restrict__ bb,
                                                   const float* __restrict__ mm,
                                                   const float* __restrict__ vv)
{
    extern __shared__ char dynsm[];
    __shared__ float sc[144], sh[144];

    const int t = threadIdx.x, lane = t & 31, w = t >> 5;
    const int wr = w & 3, wc = w >> 2;
    const int half = blockIdx.y;

    char* basep = (char*)(((uintptr_t)dynsm + 1023) & ~(uintptr_t)1023);
    const uint32_t tb = smem_u32(basep);

    if (t < 144) {
        int o = half * 144 + t;
        float s = gg[o] * rsqrtf(vv[o] + 1e-5f);
        sc[t] = s; sh[t] = bb[o] - mm[o] * s;
    }

    const unsigned char* Ath = Ahi + (size_t)blockIdx.x * A_TILE_B;
    const unsigned char* Atl = Alo + (size_t)blockIdx.x * A_TILE_B;
    const unsigned char* Bh  = Bhi + (size_t)half * BH_B;
    const unsigned char* Bl  = Blo + (size_t)half * BH_B;

    auto load_chunk = [&](int c) {
        uint32_t s = tb + (uint32_t)(c & 1) * STG;
        const unsigned char* ah = Ath + (size_t)c * A_CHUNK_B;
        const unsigned char* al = Atl + (size_t)c * A_CHUNK_B;
#pragma unroll
        for (int i = 0; i < 4; i++) {
            int e = t + 256 * i;
            cp16(s + SA_H + e * 16, ah + (size_t)e * 16);
            cp16(s + SA_L + e * 16, al + (size_t)e * 16);
        }
        const unsigned char* bh = Bh + (size_t)c * B_CHUNK_B;
        const unsigned char* bl = Bl + (size_t)c * B_CHUNK_B;
#pragma unroll
        for (int i = 0; i < 5; i++) {
            int e = t + 256 * i;
            if (e < 1152) {
                cp16(s + SB_H + e * 16, bh + (size_t)e * 16);
                cp16(s + SB_L + e * 16, bl + (size_t)e * 16);
            }
        }
    };

    float acc[2][9][4];
#pragma unroll
    for (int i = 0; i < 2; i++)
#pragma unroll
        for (int j = 0; j < 9; j++)
#pragma unroll
            for (int q = 0; q < 4; q++) acc[i][j][q] = 0.0f;

    load_chunk(0); CP_COMMIT();

    for (int c = 0; c < NCHUNK; ++c) {
        if (c + 1 < NCHUNK) { load_chunk(c + 1); CP_COMMIT(); cp_wait<1>(); }
        else                { cp_wait<0>(); }
        __syncthreads();

        const uint32_t s = tb + (uint32_t)(c & 1) * STG;
#pragma unroll
        for (int ks = 0; ks < 4; ++ks) {
            const uint32_t kb = ks * 32;
            uint32_t ahf[2][4], alf[2][4];
            {
                const int lr = lane & 15, lh = lane >> 4;
#pragma unroll
                for (int i = 0; i < 2; i++) {
                    uint32_t off = SWZ((uint32_t)((wr * 32 + i * 16 + lr) * 128 + kb + lh * 16));
                    ldmx4(ahf[i], s + SA_H + off);
                    ldmx4(alf[i], s + SA_L + off);
                }
            }
            uint32_t bhf[9][2], blf[9][2];
            {
                const int rb = (lane & 7) + ((lane >> 4) << 3);
                const int kseg = ((lane >> 3) & 1) * 16;
#pragma unroll
                for (int jj = 0; jj < 4; jj++) {
                    uint32_t off = SWZ((uint32_t)((wc * 72 + jj * 16 + rb) * 128 + kb + kseg));
                    uint32_t tmp[4];
                    ldmx4(tmp, s + SB_H + off);
                    bhf[2 * jj][0] = tmp[0]; bhf[2 * jj][1] = tmp[1];
                    bhf[2 * jj + 1][0] = tmp[2]; bhf[2 * jj + 1][1] = tmp[3];
                    ldmx4(tmp, s + SB_L + off);
                    blf[2 * jj][0] = tmp[0]; blf[2 * jj][1] = tmp[1];
                    blf[2 * jj + 1][0] = tmp[2]; blf[2 * jj + 1][1] = tmp[3];
                }
                uint32_t off8 = SWZ((uint32_t)((wc * 72 + 64 + (lane & 7)) * 128 + kb + kseg));
                ldmx2(bhf[8], s + SB_H + off8);
                ldmx2(blf[8], s + SB_L + off8);
            }
#pragma unroll
            for (int i = 0; i < 2; i++)
#pragma unroll
                for (int j = 0; j < 9; j++) {
                    mma16816(acc[i][j], ahf[i], bhf[j]);
                    mma16816(acc[i][j], ahf[i], blf[j]);
                    mma16816(acc[i][j], alf[i], bhf[j]);
                }
        }
        __syncthreads();
    }

    // ---------------- epilogue ----------------
    if (!LAST) {
        unsigned char* Oth = OutHi + (size_t)blockIdx.x * A_TILE_B;
        unsigned char* Otl = OutLo + (size_t)blockIdx.x * A_TILE_B;
#pragma unroll
        for (int i = 0; i < 2; i++) {
            const int r1 = wr * 32 + i * 16 + (lane >> 2);
#pragma unroll
            for (int j = 0; j < 9; j++) {
                const int ol = wc * 72 + j * 8 + 2 * (lane & 3);
                const int og = half * 144 + ol;
                const int chunk = og >> 6;
                const int c2 = (og & 63) * 2;
                const float s0 = sc[ol], h0 = sh[ol], s1 = sc[ol + 1], h1 = sh[ol + 1];
#pragma unroll
                for (int rh = 0; rh < 2; rh++) {
                    const int row = r1 + rh * 8;
                    float x0 = fmaxf(acc[i][j][rh * 2 + 0] * s0 + h0, 0.0f);
                    float x1 = fmaxf(acc[i][j][rh * 2 + 1] * s1 + h1, 0.0f);
                    __nv_bfloat16 hh0, ll0, hh1, ll1;
                    split_bf(x0, hh0, ll0); split_bf(x1, hh1, ll1);
                    uint32_t off = (uint32_t)chunk * A_CHUNK_B + SWZ((uint32_t)(row * 128 + c2));
                    *reinterpret_cast<uint32_t*>(Oth + off) = pack_bf(hh0, hh1);
                    *reinterpret_cast<uint32_t*>(Otl + off) = pack_bf(ll0, ll1);
                }
            }
        }
        // zero pad cols 288..319 (chunk 4 upper half) — input padding for next layer
        if (half == 0) {
            const int row = t & 127;
#pragma unroll
            for (int m = (t >> 7); m < 4; m += 2) {
                uint32_t off = 4u * A_CHUNK_B + SWZ((uint32_t)(row * 128 + 64 + m * 16));
                *reinterpret_cast<uint4*>(Oth + off) = make_uint4(0, 0, 0, 0);
                *reinterpret_cast<uint4*>(Otl + off) = make_uint4(0, 0, 0, 0);
            }
        }
    } else {
#pragma unroll
        for (int i = 0; i < 2; i++) {
            const int p0 = blockIdx.x * 128 + wr * 32 + i * 16;
            const int gidx = p0 >> 4;
            const int b = gidx >> 8, sIdx = gidx & 255;
#pragma unroll
            for (int j = 0; j < 9; j++) {
                const int ol = wc * 72 + j * 8 + 2 * (lane & 3);
                const int og = half * 144 + ol;
                const float s0 = sc[ol], h0 = sh[ol], s1 = sc[ol + 1], h1 = sh[ol + 1];
                float m0 = fmaxf(fmaxf(acc[i][j][0] * s0 + h0, 0.0f),
                                 fmaxf(acc[i][j][2] * s0 + h0, 0.0f));
                float m1 = fmaxf(fmaxf(acc[i][j][1] * s1 + h1, 0.0f),
                                 fmaxf(acc[i][j][3] * s1 + h1, 0.0f));
#pragma unroll
                for (int msk = 4; msk <= 16; msk <<= 1) {
                    m0 = fmaxf(m0, __shfl_xor_sync(0xffffffffu, m0, msk));
                    m1 = fmaxf(m1, __shfl_xor_sync(0xffffffffu, m1, msk));
                }
                if (lane < 4) {
                    OutFeat[((size_t)b * C + og) * NS + sIdx]     = m0;
                    OutFeat[((size_t)b * C + og + 1) * NS + sIdx] = m1;
                }
            }
        }
    }
}

// =================================================================================
extern "C" void kernel_launch(void* const* d_in, const int* in_sizes, int n_in,
                              void* d_out, int out_size)
{
    const float* xyz  = (const float*)d_in[0];
    const float* feat = (const float*)d_in[1];
    const float* W[3] = { (const float*)d_in[2], (const float*)d_in[7], (const float*)d_in[12] };
    const float* G[3] = { (const float*)d_in[3], (const float*)d_in[8], (const float*)d_in[13] };
    const float* Bp[3]= { (const float*)d_in[4], (const float*)d_in[9], (const float*)d_in[14] };
    const float* M[3] = { (const float*)d_in[5], (const float*)d_in[10], (const float*)d_in[15] };
    const float* V[3] = { (const float*)d_in[6], (const float*)d_in[11], (const float*)d_in[16] };

    float* out        = (float*)d_out;
    float* out_newxyz = out;
    float* out_feat   = out + NB * NS * 3;
    float* out_inds   = out + NB * NS * 3 + (size_t)NB * C * NS;

    unsigned char *Xhi, *Xlo, *Yhi, *Ylo, *Whi, *Wlo;
    cudaGetSymbolAddress((void**)&Xhi, d_Xhi);
    cudaGetSymbolAddress((void**)&Xlo, d_Xlo);
    cudaGetSymbolAddress((void**)&Yhi, d_Yhi);
    cudaGetSymbolAddress((void**)&Ylo, d_Ylo);
    cudaGetSymbolAddress((void**)&Whi, d_Whi);
    cudaGetSymbolAddress((void**)&Wlo, d_Wlo);

    cudaFuncSetAttribute(fps_kernel, cudaFuncAttributeMaxDynamicSharedMemorySize,
                         3 * NN * (int)sizeof(float));
    cudaFuncSetAttribute(mma_gemm<false>, cudaFuncAttributeMaxDynamicSharedMemorySize, DYN_SMEM);
    cudaFuncSetAttribute(mma_gemm<true>,  cudaFuncAttributeMaxDynamicSharedMemorySize, DYN_SMEM);

    const int wgrid = (C * 40 + 255) / 256;
    wprep_kernel<<<wgrid, 256>>>(W[0], 291, 1, Whi, Wlo);
    wprep_kernel<<<wgrid, 256>>>(W[1], 288, 0, Whi + W_LAYER_B, Wlo + W_LAYER_B);
    wprep_kernel<<<wgrid, 256>>>(W[2], 288, 0, Whi + 2 * W_LAYER_B, Wlo + 2 * W_LAYER_B);

    fps_kernel<<<NB, 1024, 3 * NN * sizeof(float)>>>(xyz, out_newxyz, out_inds);
    ballq_kernel<<<NB * NS / 16, 512>>>(xyz);
    gather_kernel<<<PTOT / 4, 128>>>(xyz, feat);

    mma_gemm<false><<<dim3(NTILES, 2), 256, DYN_SMEM>>>(Xhi, Xlo, Whi, Wlo,
                                                        Yhi, Ylo, nullptr,
                                                        G[0], Bp[0], M[0], V[0]);
    mma_gemm<false><<<dim3(NTILES, 2), 256, DYN_SMEM>>>(Yhi, Ylo, Whi + W_LAYER_B, Wlo + W_LAYER_B,
                                                        Xhi, Xlo, nullptr,
                                                        G[1], Bp[1], M[1], V[1]);
    mma_gemm<true><<<dim3(NTILES, 2), 256, DYN_SMEM>>>(Xhi, Xlo, Whi + 2 * W_LAYER_B, Wlo + 2 * W_LAYER_B,
                                                       nullptr, nullptr, out_feat,
                                                       G[2], Bp[2], M[2], V[2]);
}

// round 6
// speedup vs baseline: 2.1230x; 1.1945x over previous
#include <cuda_runtime.h>
#include <cuda_bf16.h>
#include <cstdint>

// Problem constants
#define NB      16
#define NN      16384
#define NS      256
#define NKS     16
#define C       288
#define PTOT    (NB*NS*NKS)      // 65536 pixels
#define NCHUNK  5                // K padded to 320 = 5 chunks of 64
#define TM      128              // pixels per GEMM CTA
#define NTILES  (PTOT/TM)        // 512

// FPS distribution
#define FPSG    8                // blocks per batch (16*8=128 <= 148 SMs: co-resident)
#define FPSPTS  (NN/FPSG)        // 2048 points per block
#define FPST    256              // threads per fps block (8 pts/thread in regs)

// byte sizes
#define A_CHUNK_B   (TM*128)             // 16384  (128 rows x 64 bf16)
#define A_TILE_B    (NCHUNK*A_CHUNK_B)   // 81920 per tile per array
#define B_CHUNK_B   (C*128)              // 36864  (288 rows x 64 bf16)
#define W_LAYER_B   (NCHUNK*B_CHUNK_B)   // 184320
#define BH_B        (144*128)            // 18432 per CTA half per chunk

// SMEM stage layout (all 1024-multiples)
#define SA_H  0u
#define SA_L  16384u
#define SB_H  32768u
#define SB_L  51200u
#define STG   69632u
#define DYN_SMEM (2*STG + 1024)          // 140288

// SW128 swizzle (within a 1024-aligned region)
#define SWZ(o) ((o) ^ (((o) >> 3) & 0x70))

// ---------------- scratch ----------------
__device__ __align__(1024) unsigned char d_Xhi[(size_t)NTILES * A_TILE_B];
__device__ __align__(1024) unsigned char d_Xlo[(size_t)NTILES * A_TILE_B];
__device__ __align__(1024) unsigned char d_Yhi[(size_t)NTILES * A_TILE_B];
__device__ __align__(1024) unsigned char d_Ylo[(size_t)NTILES * A_TILE_B];
__device__ __align__(1024) unsigned char d_Whi[3 * W_LAYER_B];
__device__ __align__(1024) unsigned char d_Wlo[3 * W_LAYER_B];
__device__ int   d_idx[PTOT];
__device__ float d_newxyz[NB * NS * 3];
__device__ unsigned long long d_fpsSlots[NB * NS * FPSG];   // per-(batch,iter,block) packed best

// ---------------- PTX helpers (all compute_80-era: safe on compute_103) ----------
__device__ __forceinline__ uint32_t smem_u32(const void* p) {
    uint32_t a;
    asm("{ .reg .u64 t; cvta.to.shared.u64 t, %1; cvt.u32.u64 %0, t; }" : "=r"(a) : "l"(p));
    return a;
}
__device__ __forceinline__ void cp16(uint32_t s, const void* g) {
    asm volatile("cp.async.cg.shared.global [%0], [%1], 16;" :: "r"(s), "l"(g) : "memory");
}
#define CP_COMMIT() asm volatile("cp.async.commit_group;" ::: "memory")
template <int N> __device__ __forceinline__ void cp_wait() {
    asm volatile("cp.async.wait_group %0;" :: "n"(N) : "memory");
}
__device__ __forceinline__ void ldmx4(uint32_t* r, uint32_t a) {
    asm volatile("ldmatrix.sync.aligned.m8n8.x4.shared.b16 {%0,%1,%2,%3}, [%4];"
                 : "=r"(r[0]), "=r"(r[1]), "=r"(r[2]), "=r"(r[3]) : "r"(a));
}
__device__ __forceinline__ void ldmx2(uint32_t* r, uint32_t a) {
    asm volatile("ldmatrix.sync.aligned.m8n8.x2.shared.b16 {%0,%1}, [%2];"
                 : "=r"(r[0]), "=r"(r[1]) : "r"(a));
}
__device__ __forceinline__ void mma16816(float* c, const uint32_t* a, const uint32_t* b) {
    asm volatile("mma.sync.aligned.m16n8k16.row.col.f32.bf16.bf16.f32 "
                 "{%0,%1,%2,%3}, {%4,%5,%6,%7}, {%8,%9}, {%0,%1,%2,%3};"
                 : "+f"(c[0]), "+f"(c[1]), "+f"(c[2]), "+f"(c[3])
                 : "r"(a[0]), "r"(a[1]), "r"(a[2]), "r"(a[3]), "r"(b[0]), "r"(b[1]));
}
__device__ __forceinline__ void split_bf(float x, __nv_bfloat16& h, __nv_bfloat16& l) {
    h = __float2bfloat16(x);
    l = __float2bfloat16(x - __bfloat162float(h));
}
__device__ __forceinline__ uint32_t pack_bf(__nv_bfloat16 a, __nv_bfloat16 b) {
    return (uint32_t)__bfloat16_as_ushort(a) | ((uint32_t)__bfloat16_as_ushort(b) << 16);
}

// =================================================================================
// 0) zero the fps sync slots (fresh every graph replay)
// =================================================================================
__global__ void zero_slots_kernel()
{
    int i = blockIdx.x * 256 + threadIdx.x;
    if (i < NB * NS * FPSG) d_fpsSlots[i] = 0ull;
}

// =================================================================================
// 1) FPS, distributed: 8 blocks/batch, coords in registers, L2 spin-sync per iter.
//    Packed key (distbits<<32)|(~idx) -> max == (max dist, tie -> lowest index).
// =================================================================================
__global__ __launch_bounds__(FPST, 1) void fps_kernel(const float* __restrict__ xyz,
                                                      float* __restrict__ out_newxyz,
                                                      float* __restrict__ out_inds)
{
    __shared__ unsigned long long warpBest[FPST / 32];
    __shared__ int sCur;

    const int b = blockIdx.x >> 3, g = blockIdx.x & 7;
    const int tid = threadIdx.x, lane = tid & 31, w = tid >> 5;
    const float* X = xyz + (size_t)b * NN * 3;
    const int n0 = g * FPSPTS + tid * 8;

    // load 8 points (24 consecutive floats) into registers
    float4 buf[6];
    const float4* src = reinterpret_cast<const float4*>(X + (size_t)n0 * 3);
#pragma unroll
    for (int i = 0; i < 6; i++) buf[i] = src[i];
    const float* bf = reinterpret_cast<const float*>(buf);
    float px[8], py[8], pz[8], dist[8];
#pragma unroll
    for (int i = 0; i < 8; i++) {
        px[i] = bf[3 * i]; py[i] = bf[3 * i + 1]; pz[i] = bf[3 * i + 2];
        dist[i] = 1e10f;
    }

    volatile unsigned long long* slots = d_fpsSlots + (size_t)b * NS * FPSG;
    int cur = 0;
    for (int it = 0; it < NS; ++it) {
        const float cx = __ldg(X + 3 * cur), cy = __ldg(X + 3 * cur + 1), cz = __ldg(X + 3 * cur + 2);
        if (g == 0 && tid == 0) {
            out_inds[b * NS + it] = (float)cur;
            int o3 = (b * NS + it) * 3;
            out_newxyz[o3] = cx; out_newxyz[o3 + 1] = cy; out_newxyz[o3 + 2] = cz;
            d_newxyz[o3]   = cx; d_newxyz[o3 + 1]   = cy; d_newxyz[o3 + 2]   = cz;
        }
        float bv = -1.0f; int bi = 0;
#pragma unroll
        for (int i = 0; i < 8; i++) {
            float dx = px[i] - cx, dy = py[i] - cy, dz = pz[i] - cz;
            float d  = dx * dx + dy * dy + dz * dz;
            float dm = fminf(dist[i], d);
            dist[i] = dm;
            if (dm > bv) { bv = dm; bi = n0 + i; }       // strict > : lowest idx on tie
        }
        unsigned long long pk = ((unsigned long long)__float_as_uint(bv) << 32)
                              | (unsigned)(0xFFFFFFFFu - (unsigned)bi);
#pragma unroll
        for (int off = 16; off; off >>= 1) {
            unsigned long long o = __shfl_down_sync(0xffffffffu, pk, off);
            if (o > pk) pk = o;
        }
        if (lane == 0) warpBest[w] = pk;
        __syncthreads();
        if (w == 0) {
            unsigned long long p2 = warpBest[lane & 7];
#pragma unroll
            for (int off = 4; off; off >>= 1) {
                unsigned long long o = __shfl_down_sync(0xffffffffu, p2, off);
                if (o > p2) p2 = o;
            }
            if (lane == 0) slots[(size_t)it * FPSG + g] = p2;   // publish (never 0)
            unsigned long long v = 0;
            if (lane < FPSG) {
                volatile unsigned long long* sl = &slots[(size_t)it * FPSG + lane];
                do { v = *sl; } while (v == 0ull);
            }
#pragma unroll
            for (int off = 4; off; off >>= 1) {
                unsigned long long o = __shfl_down_sync(0xffffffffu, v, off);
                if (o > v) v = o;
            }
            if (lane == 0) sCur = (int)(0xFFFFFFFFu - (unsigned)v);
        }
        __syncthreads();
        cur = sCur;
    }
}

// =================================================================================
// 2) Ball query (unchanged)
// =================================================================================
__global__ __launch_bounds__(512) void ballq_kernel(const float* __restrict__ xyz)
{
    __shared__ int slots[16][16];
    const int wl = threadIdx.x >> 5, lane = threadIdx.x & 31;
    const int w  = blockIdx.x * 16 + wl;
    const int b  = w >> 8;
    const float R2 = (float)(0.3 * 0.3);
    const int o3 = w * 3;
    const float nx = d_newxyz[o3], ny = d_newxyz[o3 + 1], nz = d_newxyz[o3 + 2];
    const float* pb = xyz + (size_t)b * NN * 3;

    int cnt = 0;
    for (int basei = 0; basei < NN && cnt < NKS; basei += 32) {
        int n = basei + lane;
        float dx = pb[3 * n] - nx, dy = pb[3 * n + 1] - ny, dz = pb[3 * n + 2] - nz;
        float d2 = dx * dx + dy * dy + dz * dz;
        bool in = d2 < R2;
        unsigned m = __ballot_sync(0xffffffffu, in);
        int pos = cnt + __popc(m & ((1u << lane) - 1u));
        if (in && pos < NKS) slots[wl][pos] = n;
        cnt += __popc(m);
    }
    __syncwarp();
    int first = slots[wl][0];
    if (lane < NKS && lane >= cnt) slots[wl][lane] = first;
    __syncwarp();
    if (lane < NKS) d_idx[w * NKS + lane] = slots[wl][lane];
}

// =================================================================================
// 3) Weight prep (unchanged): fp32 W -> bf16 hi/lo, chunked SW128, layer0 permute
// =================================================================================
__global__ __launch_bounds__(256) void wprep_kernel(const float* __restrict__ W, int Kdim,
                                                    int perm0, unsigned char* __restrict__ whi,
                                                    unsigned char* __restrict__ wlo)
{
    int id = blockIdx.x * 256 + threadIdx.x;
    if (id >= C * 40) return;
    int o = id / 40, u = id % 40;
    uint32_t h[4], l[4];
#pragma unroll
    for (int e = 0; e < 4; e++) {
        __nv_bfloat16 hh[2], ll[2];
#pragma unroll
        for (int q = 0; q < 2; q++) {
            int c = u * 8 + e * 2 + q;
            int src;
            if (perm0) src = (c < 288) ? c + 3 : ((c < 291) ? c - 288 : -1);
            else       src = (c < Kdim) ? c : -1;
            float v = (src >= 0) ? W[o * Kdim + src] : 0.0f;
            split_bf(v, hh[q], ll[q]);
        }
        h[e] = pack_bf(hh[0], hh[1]);
        l[e] = pack_bf(ll[0], ll[1]);
    }
    size_t off = (size_t)(u / 8) * B_CHUNK_B + SWZ((uint32_t)(o * 128 + (u % 8) * 16));
    *reinterpret_cast<uint4*>(whi + off) = make_uint4(h[0], h[1], h[2], h[3]);
    *reinterpret_cast<uint4*>(wlo + off) = make_uint4(l[0], l[1], l[2], l[3]);
}

// =================================================================================
// 4) Gather (unchanged): layer-0 A tiles (bf16 hi/lo, swizzled chunk layout)
// =================================================================================
__global__ __launch_bounds__(128) void gather_kernel(const float* __restrict__ xyz,
                                                     const float* __restrict__ feat)
{
    __shared__ __align__(16) __nv_bfloat16 sH[4][320];
    __shared__ __align__(16) __nv_bfloat16 sL[4][320];
    const int wid = threadIdx.x >> 5, lane = threadIdx.x & 31;
    const int p = blockIdx.x * 4 + wid;
    const int b = p >> 12, s = (p >> 4) & 255;
    const int j = d_idx[p];

    const float* fb = feat + (size_t)b * C * NN + j;
#pragma unroll
    for (int r = 0; r < 9; r++) {
        int c = lane + 32 * r;
        float f = fb[(size_t)c * NN];
        __nv_bfloat16 h, l; split_bf(f, h, l);
        sH[wid][c] = h; sL[wid][c] = l;
    }
    if (lane < 3) {
        float gv = xyz[((size_t)b * NN + j) * 3 + lane];
        float cv = d_newxyz[(b * NS + s) * 3 + lane];
        float rel = (gv - cv) / 0.3f;
        __nv_bfloat16 h, l; split_bf(rel, h, l);
        sH[wid][288 + lane] = h; sL[wid][288 + lane] = l;
    } else {
        sH[wid][288 + lane] = __ushort_as_bfloat16(0);
        sL[wid][288 + lane] = __ushort_as_bfloat16(0);
    }
    __syncwarp();

    const size_t tbase = (size_t)(p >> 7) * A_TILE_B;
    const int row = p & 127;
    const char* srcH = reinterpret_cast<const char*>(&sH[wid][0]);
    const char* srcL = reinterpret_cast<const char*>(&sL[wid][0]);
#pragma unroll
    for (int u = lane; u < 40; u += 32) {
        size_t off = tbase + (size_t)(u / 8) * A_CHUNK_B + SWZ((uint32_t)(row * 128 + (u % 8) * 16));
        *reinterpret_cast<uint4*>(d_Xhi + off) = *reinterpret_cast<const uint4*>(srcH + u * 16);
        *reinterpret_cast<uint4*>(d_Xlo + off) = *reinterpret_cast<const uint4*>(srcL + u * 16);
    }
}

// =================================================================================
// 5) GEMM + BN + ReLU via mma.sync bf16 hi/lo split (unchanged from R5 — passing)
// =================================================================================
template <bool LAST>
__global__ __launch_bounds__(256, 1) void mma_gemm(const unsigned char* __restrict__ Ahi,
                                                   const unsigned char* __restrict__ Alo,
                                                   const unsigned char* __restrict__ Bhi,
                                                   const unsigned char* __restrict__ Blo,
                                                   unsigned char* __restrict__ OutHi,
                                                   unsigned char* __restrict__ OutLo,
                                                   float* __restrict__ OutFeat,
                                                   const float* __restrict__ gg,
                                                   const float* __restrict__ bb,
                                                   const float* __restrict__ mm,
                                                   const float* __restrict__ vv)
{
    extern __shared__ char dynsm[];
    __shared__ float sc[144], sh[144];

    const int t = threadIdx.x, lane = t & 31, w = t >> 5;
    const int wr = w & 3, wc = w >> 2;
    const int half = blockIdx.y;

    char* basep = (char*)(((uintptr_t)dynsm + 1023) & ~(uintptr_t)1023);
    const uint32_t tb = smem_u32(basep);

    if (t < 144) {
        int o = half * 144 + t;
        float s = gg[o] * rsqrtf(vv[o] + 1e-5f);
        sc[t] = s; sh[t] = bb[o] - mm[o] * s;
    }

    const unsigned char* Ath = Ahi + (size_t)blockIdx.x * A_TILE_B;
    const unsigned char* Atl = Alo + (size_t)blockIdx.x * A_TILE_B;
    const unsigned char* Bh  = Bhi + (size_t)half * BH_B;
    const unsigned char* Bl  = Blo + (size_t)half * BH_B;

    auto load_chunk = [&](int c) {
        uint32_t s = tb + (uint32_t)(c & 1) * STG;
        const unsigned char* ah = Ath + (size_t)c * A_CHUNK_B;
        const unsigned char* al = Atl + (size_t)c * A_CHUNK_B;
#pragma unroll
        for (int i = 0; i < 4; i++) {
            int e = t + 256 * i;
            cp16(s + SA_H + e * 16, ah + (size_t)e * 16);
            cp16(s + SA_L + e * 16, al + (size_t)e * 16);
        }
        const unsigned char* bh = Bh + (size_t)c * B_CHUNK_B;
        const unsigned char* bl = Bl + (size_t)c * B_CHUNK_B;
#pragma unroll
        for (int i = 0; i < 5; i++) {
            int e = t + 256 * i;
            if (e < 1152) {
                cp16(s + SB_H + e * 16, bh + (size_t)e * 16);
                cp16(s + SB_L + e * 16, bl + (size_t)e * 16);
            }
        }
    };

    float acc[2][9][4];
#pragma unroll
    for (int i = 0; i < 2; i++)
#pragma unroll
        for (int j = 0; j < 9; j++)
#pragma unroll
            for (int q = 0; q < 4; q++) acc[i][j][q] = 0.0f;

    load_chunk(0); CP_COMMIT();

    for (int c = 0; c < NCHUNK; ++c) {
        if (c + 1 < NCHUNK) { load_chunk(c + 1); CP_COMMIT(); cp_wait<1>(); }
        else                { cp_wait<0>(); }
        __syncthreads();

        const uint32_t s = tb + (uint32_t)(c & 1) * STG;
#pragma unroll
        for (int ks = 0; ks < 4; ++ks) {
            const uint32_t kb = ks * 32;
            uint32_t ahf[2][4], alf[2][4];
            {
                const int lr = lane & 15, lh = lane >> 4;
#pragma unroll
                for (int i = 0; i < 2; i++) {
                    uint32_t off = SWZ((uint32_t)((wr * 32 + i * 16 + lr) * 128 + kb + lh * 16));
                    ldmx4(ahf[i], s + SA_H + off);
                    ldmx4(alf[i], s + SA_L + off);
                }
            }
            uint32_t bhf[9][2], blf[9][2];
            {
                const int rb = (lane & 7) + ((lane >> 4) << 3);
                const int kseg = ((lane >> 3) & 1) * 16;
#pragma unroll
                for (int jj = 0; jj < 4; jj++) {
                    uint32_t off = SWZ((uint32_t)((wc * 72 + jj * 16 + rb) * 128 + kb + kseg));
                    uint32_t tmp[4];
                    ldmx4(tmp, s + SB_H + off);
                    bhf[2 * jj][0] = tmp[0]; bhf[2 * jj][1] = tmp[1];
                    bhf[2 * jj + 1][0] = tmp[2]; bhf[2 * jj + 1][1] = tmp[3];
                    ldmx4(tmp, s + SB_L + off);
                    blf[2 * jj][0] = tmp[0]; blf[2 * jj][1] = tmp[1];
                    blf[2 * jj + 1][0] = tmp[2]; blf[2 * jj + 1][1] = tmp[3];
                }
                uint32_t off8 = SWZ((uint32_t)((wc * 72 + 64 + (lane & 7)) * 128 + kb + kseg));
                ldmx2(bhf[8], s + SB_H + off8);
                ldmx2(blf[8], s + SB_L + off8);
            }
#pragma unroll
            for (int i = 0; i < 2; i++)
#pragma unroll
                for (int j = 0; j < 9; j++) {
                    mma16816(acc[i][j], ahf[i], bhf[j]);
                    mma16816(acc[i][j], ahf[i], blf[j]);
                    mma16816(acc[i][j], alf[i], bhf[j]);
                }
        }
        __syncthreads();
    }

    // ---------------- epilogue ----------------
    if (!LAST) {
        unsigned char* Oth = OutHi + (size_t)blockIdx.x * A_TILE_B;
        unsigned char* Otl = OutLo + (size_t)blockIdx.x * A_TILE_B;
#pragma unroll
        for (int i = 0; i < 2; i++) {
            const int r1 = wr * 32 + i * 16 + (lane >> 2);
#pragma unroll
            for (int j = 0; j < 9; j++) {
                const int ol = wc * 72 + j * 8 + 2 * (lane & 3);
                const int og = half * 144 + ol;
                const int chunk = og >> 6;
                const int c2 = (og & 63) * 2;
                const float s0 = sc[ol], h0 = sh[ol], s1 = sc[ol + 1], h1 = sh[ol + 1];
#pragma unroll
                for (int rh = 0; rh < 2; rh++) {
                    const int row = r1 + rh * 8;
                    float x0 = fmaxf(acc[i][j][rh * 2 + 0] * s0 + h0, 0.0f);
                    float x1 = fmaxf(acc[i][j][rh * 2 + 1] * s1 + h1, 0.0f);
                    __nv_bfloat16 hh0, ll0, hh1, ll1;
                    split_bf(x0, hh0, ll0); split_bf(x1, hh1, ll1);
                    uint32_t off = (uint32_t)chunk * A_CHUNK_B + SWZ((uint32_t)(row * 128 + c2));
                    *reinterpret_cast<uint32_t*>(Oth + off) = pack_bf(hh0, hh1);
                    *reinterpret_cast<uint32_t*>(Otl + off) = pack_bf(ll0, ll1);
                }
            }
        }
        if (half == 0) {
            const int row = t & 127;
#pragma unroll
            for (int m = (t >> 7); m < 4; m += 2) {
                uint32_t off = 4u * A_CHUNK_B + SWZ((uint32_t)(row * 128 + 64 + m * 16));
                *reinterpret_cast<uint4*>(Oth + off) = make_uint4(0, 0, 0, 0);
                *reinterpret_cast<uint4*>(Otl + off) = make_uint4(0, 0, 0, 0);
            }
        }
    } else {
#pragma unroll
        for (int i = 0; i < 2; i++) {
            const int p0 = blockIdx.x * 128 + wr * 32 + i * 16;
            const int gidx = p0 >> 4;
            const int b = gidx >> 8, sIdx = gidx & 255;
#pragma unroll
            for (int j = 0; j < 9; j++) {
                const int ol = wc * 72 + j * 8 + 2 * (lane & 3);
                const int og = half * 144 + ol;
                const float s0 = sc[ol], h0 = sh[ol], s1 = sc[ol + 1], h1 = sh[ol + 1];
                float m0 = fmaxf(fmaxf(acc[i][j][0] * s0 + h0, 0.0f),
                                 fmaxf(acc[i][j][2] * s0 + h0, 0.0f));
                float m1 = fmaxf(fmaxf(acc[i][j][1] * s1 + h1, 0.0f),
                                 fmaxf(acc[i][j][3] * s1 + h1, 0.0f));
#pragma unroll
                for (int msk = 4; msk <= 16; msk <<= 1) {
                    m0 = fmaxf(m0, __shfl_xor_sync(0xffffffffu, m0, msk));
                    m1 = fmaxf(m1, __shfl_xor_sync(0xffffffffu, m1, msk));
                }
                if (lane < 4) {
                    OutFeat[((size_t)b * C + og) * NS + sIdx]     = m0;
                    OutFeat[((size_t)b * C + og + 1) * NS + sIdx] = m1;
                }
            }
        }
    }
}

// =================================================================================
extern "C" void kernel_launch(void* const* d_in, const int* in_sizes, int n_in,
                              void* d_out, int out_size)
{
    const float* xyz  = (const float*)d_in[0];
    const float* feat = (const float*)d_in[1];
    const float* W[3] = { (const float*)d_in[2], (const float*)d_in[7], (const float*)d_in[12] };
    const float* G[3] = { (const float*)d_in[3], (const float*)d_in[8], (const float*)d_in[13] };
    const float* Bp[3]= { (const float*)d_in[4], (const float*)d_in[9], (const float*)d_in[14] };
    const float* M[3] = { (const float*)d_in[5], (const float*)d_in[10], (const float*)d_in[15] };
    const float* V[3] = { (const float*)d_in[6], (const float*)d_in[11], (const float*)d_in[16] };

    float* out        = (float*)d_out;
    float* out_newxyz = out;
    float* out_feat   = out + NB * NS * 3;
    float* out_inds   = out + NB * NS * 3 + (size_t)NB * C * NS;

    unsigned char *Xhi, *Xlo, *Yhi, *Ylo, *Whi, *Wlo;
    cudaGetSymbolAddress((void**)&Xhi, d_Xhi);
    cudaGetSymbolAddress((void**)&Xlo, d_Xlo);
    cudaGetSymbolAddress((void**)&Yhi, d_Yhi);
    cudaGetSymbolAddress((void**)&Ylo, d_Ylo);
    cudaGetSymbolAddress((void**)&Whi, d_Whi);
    cudaGetSymbolAddress((void**)&Wlo, d_Wlo);

    cudaFuncSetAttribute(mma_gemm<false>, cudaFuncAttributeMaxDynamicSharedMemorySize, DYN_SMEM);
    cudaFuncSetAttribute(mma_gemm<true>,  cudaFuncAttributeMaxDynamicSharedMemorySize, DYN_SMEM);

    const int wgrid = (C * 40 + 255) / 256;
    wprep_kernel<<<wgrid, 256>>>(W[0], 291, 1, Whi, Wlo);
    wprep_kernel<<<wgrid, 256>>>(W[1], 288, 0, Whi + W_LAYER_B, Wlo + W_LAYER_B);
    wprep_kernel<<<wgrid, 256>>>(W[2], 288, 0, Whi + 2 * W_LAYER_B, Wlo + 2 * W_LAYER_B);

    zero_slots_kernel<<<(NB * NS * FPSG + 255) / 256, 256>>>();
    fps_kernel<<<NB * FPSG, FPST>>>(xyz, out_newxyz, out_inds);
    ballq_kernel<<<NB * NS / 16, 512>>>(xyz);
    gather_kernel<<<PTOT / 4, 128>>>(xyz, feat);

    mma_gemm<false><<<dim3(NTILES, 2), 256, DYN_SMEM>>>(Xhi, Xlo, Whi, Wlo,
                                                        Yhi, Ylo, nullptr,
                                                        G[0], Bp[0], M[0], V[0]);
    mma_gemm<false><<<dim3(NTILES, 2), 256, DYN_SMEM>>>(Yhi, Ylo, Whi + W_LAYER_B, Wlo + W_LAYER_B,
                                                        Xhi, Xlo, nullptr,
                                                        G[1], Bp[1], M[1], V[1]);
    mma_gemm<true><<<dim3(NTILES, 2), 256, DYN_SMEM>>>(Xhi, Xlo, Whi + 2 * W_LAYER_B, Wlo + 2 * W_LAYER_B,
                                                       nullptr, nullptr, out_feat,
                                                       G[2], Bp[2], M[2], V[2]);
}